// round 11
// baseline (speedup 1.0000x reference)
#include <cuda_runtime.h>

#define S 26
#define D 7
#define DA 11
#define V 29
#define NW 13
#define NT (NW * 32)   // 416 threads: 2 rows per warp
#define LOG2E 1.4426950408889634f
#define FULL 0xFFFFFFFFu

__device__ __forceinline__ float ex2(float x) {
    float y; asm("ex2.approx.f32 %0, %1;" : "=f"(y) : "f"(x)); return y;
}
__device__ __forceinline__ float rcpa(float x) {
    float y; asm("rcp.approx.f32 %0, %1;" : "=f"(y) : "f"(x)); return y;
}

__global__ __launch_bounds__(NT, 1)
void bes_transformer_kernel(
    const int*   __restrict__ x,
    const float* __restrict__ emb_table,
    const float* __restrict__ pos,
    const float* __restrict__ wk0, const float* __restrict__ bk0,
    const float* __restrict__ wq0, const float* __restrict__ bq0,
    const float* __restrict__ wv0, const float* __restrict__ bv0,
    const float* __restrict__ wf0, const float* __restrict__ bf0,
    const float* __restrict__ wk1, const float* __restrict__ bk1,
    const float* __restrict__ wq1, const float* __restrict__ bq1,
    const float* __restrict__ wv1, const float* __restrict__ bv1,
    const float* __restrict__ wf1, const float* __restrict__ bf1,
    const float* __restrict__ wout, const float* __restrict__ bout,
    float* __restrict__ out)
{
    __shared__ float h[S][D];                 // warp-private rows
    __shared__ float kk[2][S][DA];            // double-buffered per layer
    __shared__ float qq[2][S][DA];            // (pre-scaled by log2e)
    __shared__ float vv[2][S][DA];
    __shared__ float att[S][S];               // warp-private rows
    __shared__ float res[S][DA];              // warp-private rows

    const int t    = threadIdx.x;
    const int w    = t >> 5;
    const int lane = t & 31;
    const int r0   = 2 * w;
    const int r1   = r0 + 1;
    const int hi   = lane - 16;

    // ---- embedding + positional (warp-local) ----
    if (lane < D)
        h[r0][lane] = emb_table[x[r0] * D + lane] + pos[r0 * D + lane];
    else if (hi >= 0 && hi < D)
        h[r1][hi]   = emb_table[x[r1] * D + hi]   + pos[r1 * D + hi];
    __syncwarp();

    float iv_keep0 = 0.f, iv_keep1 = 0.f;     // layer-1 row inverses

    #pragma unroll 1
    for (int layer = 0; layer < 2; layer++) {
        const float* wk = layer ? wk1 : wk0;
        const float* bk = layer ? bk1 : bk0;
        const float* wq = layer ? wq1 : wq0;
        const float* bq = layer ? bq1 : bq0;
        const float* wv = layer ? wv1 : wv0;
        const float* bv = layer ? bv1 : bv0;
        const float* wf = layer ? wf1 : wf0;
        const float* bf = layer ? bf1 : bf0;

        // ---- QKV projections (warp-local rows) ----
        if (lane < DA) {
            int a = lane;
            float sk = bk[a], sq = bq[a], sv = bv[a];
            #pragma unroll
            for (int d = 0; d < D; d++) {
                float hv = h[r0][d];
                sk += hv * wk[a * D + d];
                sq += hv * wq[a * D + d];
                sv += hv * wv[a * D + d];
            }
            kk[layer][r0][a] = sk; qq[layer][r0][a] = sq * LOG2E; vv[layer][r0][a] = sv;
        } else if (hi >= 0 && hi < DA) {
            int a = hi;
            float sk = bk[a], sq = bq[a], sv = bv[a];
            #pragma unroll
            for (int d = 0; d < D; d++) {
                float hv = h[r1][d];
                sk += hv * wk[a * D + d];
                sq += hv * wq[a * D + d];
                sv += hv * wv[a * D + d];
            }
            kk[layer][r1][a] = sk; qq[layer][r1][a] = sq * LOG2E; vv[layer][r1][a] = sv;
        }
        __syncthreads();   // ===== only block barrier this layer: k/q/v visible =====

        // ---- scores for both owned rows (lanes = columns, great ILP) ----
        if (lane <= r0) {
            float s = 0.f;
            #pragma unroll
            for (int a = 0; a < DA; a++) s += qq[layer][r0][a] * kk[layer][lane][a];
            att[r0][lane] = ex2(s);
        }
        if (lane <= r1) {
            float s = 0.f;
            #pragma unroll
            for (int a = 0; a < DA; a++) s += qq[layer][r1][a] * kk[layer][lane][a];
            att[r1][lane] = ex2(s);
        }
        __syncwarp();

        // ---- AV + normalize (row-local att, cross-row v already fenced) ----
        float ivl = 0.f, ivh = 0.f;
        if (lane < DA) {
            float sum = 0.f, dot = 0.f;
            for (int c = 0; c <= r0; c++) {
                float e = att[r0][c];
                sum += e;
                dot += e * vv[layer][c][lane];
            }
            ivl = rcpa(sum);
            res[r0][lane] = dot * ivl;
        } else if (hi >= 0 && hi < DA) {
            float sum = 0.f, dot = 0.f;
            for (int c = 0; c <= r1; c++) {
                float e = att[r1][c];
                sum += e;
                dot += e * vv[layer][c][hi];
            }
            ivh = rcpa(sum);
            res[r1][hi] = dot * ivh;
        }
        if (layer == 1) { iv_keep0 = ivl; iv_keep1 = ivh; }
        __syncwarp();

        // ---- output projection -> h (warp-local) ----
        if (lane < D) {
            float val = bf[lane];
            #pragma unroll
            for (int a = 0; a < DA; a++) val += res[r0][a] * wf[lane * DA + a];
            h[r0][lane] = val;
        } else if (hi >= 0 && hi < D) {
            float val = bf[hi];
            #pragma unroll
            for (int a = 0; a < DA; a++) val += res[r1][a] * wf[hi * DA + a];
            h[r1][hi] = val;
        }
        __syncwarp();
    }

    // ---- layer-1 attention rows to output (iv via shuffle) ----
    float iv0 = __shfl_sync(FULL, iv_keep0, 0);
    float iv1 = __shfl_sync(FULL, iv_keep1, 16);
    if (lane < S) {
        out[S * V + r0 * S + lane] = (lane <= r0) ? att[r0][lane] * iv0 : 0.f;
        out[S * V + r1 * S + lane] = (lane <= r1) ? att[r1][lane] * iv1 : 0.f;
    }

    // ---- logits for both owned rows ----
    if (lane < V) {
        float v0 = bout[lane], v1 = v0;
        #pragma unroll
        for (int d = 0; d < D; d++) {
            float wv_ = wout[lane * D + d];
            v0 += h[r0][d] * wv_;
            v1 += h[r1][d] * wv_;
        }
        out[r0 * V + lane] = v0;
        out[r1 * V + lane] = v1;
    }
}

extern "C" void kernel_launch(void* const* d_in, const int* in_sizes, int n_in,
                              void* d_out, int out_size)
{
    bes_transformer_kernel<<<1, NT>>>(
        (const int*)  d_in[0],   // x
        (const float*)d_in[1],   // emb_table
        (const float*)d_in[2],   // pos
        (const float*)d_in[3],  (const float*)d_in[4],   // w_k0, b_k0
        (const float*)d_in[5],  (const float*)d_in[6],   // w_q0, b_q0
        (const float*)d_in[7],  (const float*)d_in[8],   // w_v0, b_v0
        (const float*)d_in[9],  (const float*)d_in[10],  // w_f0, b_f0
        (const float*)d_in[11], (const float*)d_in[12],  // w_k1, b_k1
        (const float*)d_in[13], (const float*)d_in[14],  // w_q1, b_q1
        (const float*)d_in[15], (const float*)d_in[16],  // w_v1, b_v1
        (const float*)d_in[17], (const float*)d_in[18],  // w_f1, b_f1
        (const float*)d_in[19], (const float*)d_in[20],  // w_out, b_out
        (float*)d_out);
}

// round 12
// speedup vs baseline: 1.1408x; 1.1408x over previous
#include <cuda_runtime.h>

#define S 26
#define D 7
#define DA 11
#define V 29
#define NT 384
#define TRI (S*(S+1)/2)          // 351
#define SB  (TRI + S*D)          // 533: scores + vw work items
#define LOG2E 1.4426950408889634f

__device__ __forceinline__ float ex2(float x) {
    float y; asm("ex2.approx.f32 %0, %1;" : "=f"(y) : "f"(x)); return y;
}
__device__ __forceinline__ float rcpa(float x) {
    float y; asm("rcp.approx.f32 %0, %1;" : "=f"(y) : "f"(x)); return y;
}

__global__ __launch_bounds__(NT, 1)
void bes_transformer_kernel(
    const int*   __restrict__ x,
    const float* __restrict__ emb_table,
    const float* __restrict__ pos,
    const float* __restrict__ wk0, const float* __restrict__ bk0,
    const float* __restrict__ wq0, const float* __restrict__ bq0,
    const float* __restrict__ wv0, const float* __restrict__ bv0,
    const float* __restrict__ wf0, const float* __restrict__ bf0,
    const float* __restrict__ wk1, const float* __restrict__ bk1,
    const float* __restrict__ wq1, const float* __restrict__ bq1,
    const float* __restrict__ wv1, const float* __restrict__ bv1,
    const float* __restrict__ wf1, const float* __restrict__ bf1,
    const float* __restrict__ wout, const float* __restrict__ bout,
    float* __restrict__ out)
{
    __shared__ float h[S][D];
    __shared__ float k[S][DA];
    __shared__ float q[S][DA];    // pre-scaled by log2e
    __shared__ float v[S][DA];
    __shared__ float att[S][S];   // lower triangle valid, upper garbage
    __shared__ float vw[S][D];    // v @ wf^T  (narrow-direction fusion)
    __shared__ float inv_s[S];

    const int t = threadIdx.x;

    // ===== stage 0: fused embedding + QKV layer 0 (286 threads) ===========
    if (t < S * DA) {
        int s = t / DA, a = t % DA;
        int xv = x[s];
        float sk = bk0[a], sq = bq0[a], sv = bv0[a];
        #pragma unroll
        for (int d = 0; d < D; d++) {
            float hv = emb_table[xv * D + d] + pos[s * D + d];
            sk += hv * wk0[a * D + d];
            sq += hv * wq0[a * D + d];
            sv += hv * wv0[a * D + d];
        }
        k[s][a] = sk; q[s][a] = sq * LOG2E; v[s][a] = sv;
    }
    __syncthreads();

    #pragma unroll 1
    for (int layer = 0; layer < 2; layer++) {
        const float* wf = layer ? wf1 : wf0;
        const float* bf = layer ? bf1 : bf0;

        // ===== stage B: scores (packed triangle) + vw precompute ==========
        for (int i = t; i < SB; i += NT) {
            if (i < TRI) {
                int tr = (int)((sqrtf(8.f * (float)i + 1.f) - 1.f) * 0.5f);
                if (i < tr * (tr + 1) / 2) tr--;
                if (i >= (tr + 1) * (tr + 2) / 2) tr++;
                int tc = i - tr * (tr + 1) / 2;
                float sum = 0.f;
                #pragma unroll
                for (int a = 0; a < DA; a++) sum += q[tr][a] * k[tc][a];
                att[tr][tc] = ex2(sum);
            } else {
                int j = i - TRI, c = j / D, d = j % D;
                float acc = 0.f;
                #pragma unroll
                for (int a = 0; a < DA; a++) acc += v[c][a] * wf[d * DA + a];
                vw[c][d] = acc;
            }
        }
        __syncthreads();

        // ===== stage C: h[s][d] = bf + iv * sum_c att*vw  (182 threads) ====
        if (t < S * D) {
            int s = t / D, d = t % D;
            float sum = 0.f, dot = 0.f;
            for (int c = 0; c <= s; c++) {
                float e = att[s][c];
                sum += e;
                dot += e * vw[c][d];
            }
            float iv = rcpa(sum);
            h[s][d] = bf[d] + iv * dot;
            if (layer == 1 && d == 0) inv_s[s] = iv;
        }
        __syncthreads();

        // ===== stage D (layer 0 only): QKV layer 1 from h =================
        if (layer == 0) {
            if (t < S * DA) {
                int s = t / DA, a = t % DA;
                float sk = bk1[a], sq = bq1[a], sv = bv1[a];
                #pragma unroll
                for (int d = 0; d < D; d++) {
                    float hv = h[s][d];
                    sk += hv * wk1[a * D + d];
                    sq += hv * wq1[a * D + d];
                    sv += hv * wv1[a * D + d];
                }
                k[s][a] = sk; q[s][a] = sq * LOG2E; v[s][a] = sv;
            }
            __syncthreads();
        }
    }

    // ===== final stage: logits + normalized attention matrix ==============
    for (int i = t; i < S * V; i += NT) {
        int s = i / V, vv = i % V;
        float r = bout[vv];
        #pragma unroll
        for (int d = 0; d < D; d++) r += h[s][d] * wout[vv * D + d];
        out[i] = r;
    }
    for (int i = t; i < S * S; i += NT) {
        int r = i / S, c = i % S;
        out[S * V + i] = (c <= r) ? att[r][c] * inv_s[r] : 0.f;
    }
}

extern "C" void kernel_launch(void* const* d_in, const int* in_sizes, int n_in,
                              void* d_out, int out_size)
{
    bes_transformer_kernel<<<1, NT>>>(
        (const int*)  d_in[0],   // x
        (const float*)d_in[1],   // emb_table
        (const float*)d_in[2],   // pos
        (const float*)d_in[3],  (const float*)d_in[4],   // w_k0, b_k0
        (const float*)d_in[5],  (const float*)d_in[6],   // w_q0, b_q0
        (const float*)d_in[7],  (const float*)d_in[8],   // w_v0, b_v0
        (const float*)d_in[9],  (const float*)d_in[10],  // w_f0, b_f0
        (const float*)d_in[11], (const float*)d_in[12],  // w_k1, b_k1
        (const float*)d_in[13], (const float*)d_in[14],  // w_q1, b_q1
        (const float*)d_in[15], (const float*)d_in[16],  // w_v1, b_v1
        (const float*)d_in[17], (const float*)d_in[18],  // w_f1, b_f1
        (const float*)d_in[19], (const float*)d_in[20],  // w_out, b_out
        (float*)d_out);
}

// round 13
// speedup vs baseline: 1.2154x; 1.0654x over previous
#include <cuda_runtime.h>

#define S 26
#define D 7
#define DA 11
#define V 29
#define NT 384
#define TRI (S*(S+1)/2)   // 351
#define LOG2E 1.4426950408889634f

__device__ __forceinline__ float ex2(float x) {
    float y; asm("ex2.approx.f32 %0, %1;" : "=f"(y) : "f"(x)); return y;
}
__device__ __forceinline__ float rcpa(float x) {
    float y; asm("rcp.approx.f32 %0, %1;" : "=f"(y) : "f"(x)); return y;
}

__global__ __launch_bounds__(NT, 1)
void bes_transformer_kernel(
    const int*   __restrict__ x,
    const float* __restrict__ emb_table,
    const float* __restrict__ pos,
    const float* __restrict__ wk0, const float* __restrict__ bk0,
    const float* __restrict__ wq0, const float* __restrict__ bq0,
    const float* __restrict__ wv0, const float* __restrict__ bv0,
    const float* __restrict__ wf0, const float* __restrict__ bf0,
    const float* __restrict__ wk1, const float* __restrict__ bk1,
    const float* __restrict__ wq1, const float* __restrict__ bq1,
    const float* __restrict__ wv1, const float* __restrict__ bv1,
    const float* __restrict__ wf1, const float* __restrict__ bf1,
    const float* __restrict__ wout, const float* __restrict__ bout,
    float* __restrict__ out)
{
    __shared__ float h[S][D];
    __shared__ float k[S][DA];
    __shared__ float q[S][DA];    // pre-scaled by log2(e)
    __shared__ float v[S][DA];
    __shared__ float att[S][S];   // lower triangle valid; upper garbage
    __shared__ float res[S][DA];
    __shared__ float inv_s[S];

    const int t = threadIdx.x;

    // packed lower-triangle coords (t < TRI)
    int tr = 0, tc = 0;
    if (t < TRI) {
        tr = (int)((sqrtf(8.f * (float)t + 1.f) - 1.f) * 0.5f);
        if (t < tr * (tr + 1) / 2) tr--;
        if (t >= (tr + 1) * (tr + 2) / 2) tr++;
        tc = t - tr * (tr + 1) / 2;
    }

    // ===== entry-time register prefetch of per-thread weight roles =========
    // QKV role: t < 286, row a = t % 11 of each 11x7 weight matrix.
    float pk0[D], pq0[D], pv0[D], pk1[D], pq1[D], pv1[D];
    float bk0r = 0.f, bq0r = 0.f, bv0r = 0.f, bk1r = 0.f, bq1r = 0.f, bv1r = 0.f;
    if (t < S * DA) {
        int a = t % DA;
        #pragma unroll
        for (int d = 0; d < D; d++) {
            pk0[d] = wk0[a * D + d];
            pq0[d] = wq0[a * D + d];
            pv0[d] = wv0[a * D + d];
            pk1[d] = wk1[a * D + d];
            pq1[d] = wq1[a * D + d];
            pv1[d] = wv1[a * D + d];
        }
        bk0r = bk0[a]; bq0r = bq0[a]; bv0r = bv0[a];
        bk1r = bk1[a]; bq1r = bq1[a]; bv1r = bv1[a];
    }
    // proj role: t < 182, row d = t % 7 of each 7x11 wf matrix.
    float pf0[DA], pf1[DA];
    float bf0r = 0.f, bf1r = 0.f;
    if (t < S * D) {
        int d = t % D;
        #pragma unroll
        for (int a = 0; a < DA; a++) {
            pf0[a] = wf0[d * DA + a];
            pf1[a] = wf1[d * DA + a];
        }
        bf0r = bf0[d]; bf1r = bf1[d];
    }

    // ---- stage 0: embedding + positional ----
    if (t < S * D) {
        int s = t / D, d = t % D;
        h[s][d] = emb_table[x[s] * D + d] + pos[t];
    }
    __syncthreads();

    // ---- stage 1: QKV layer 0 (prefetched weights) ----
    if (t < S * DA) {
        int s = t / DA;
        float sk = bk0r, sq = bq0r, sv = bv0r;
        #pragma unroll
        for (int d = 0; d < D; d++) {
            float hv = h[s][d];
            sk += hv * pk0[d];
            sq += hv * pq0[d];
            sv += hv * pv0[d];
        }
        k[s][t % DA] = sk; q[s][t % DA] = sq * LOG2E; v[s][t % DA] = sv;
    }
    __syncthreads();

    // ---- stage 2: scores 0 (packed triangle, ex2) ----
    if (t < TRI) {
        float sum = 0.f;
        #pragma unroll
        for (int a = 0; a < DA; a++) sum += q[tr][a] * k[tc][a];
        att[tr][tc] = ex2(sum);
    }
    __syncthreads();

    // ---- stage 3: AV0 + normalize ----
    if (t < S * DA) {
        int s = t / DA, a = t % DA;
        float sum = 0.f, dot = 0.f;
        for (int c = 0; c <= s; c++) {
            float e = att[s][c];
            sum += e;
            dot += e * v[c][a];
        }
        res[s][a] = dot * rcpa(sum);
    }
    __syncthreads();

    // ---- stage 4: proj0 -> h (prefetched wf0) ----
    if (t < S * D) {
        int s = t / D;
        float r = bf0r;
        #pragma unroll
        for (int a = 0; a < DA; a++) r += res[s][a] * pf0[a];
        h[s][t % D] = r;
    }
    __syncthreads();

    // ---- stage 5: QKV layer 1 (prefetched weights) ----
    if (t < S * DA) {
        int s = t / DA;
        float sk = bk1r, sq = bq1r, sv = bv1r;
        #pragma unroll
        for (int d = 0; d < D; d++) {
            float hv = h[s][d];
            sk += hv * pk1[d];
            sq += hv * pq1[d];
            sv += hv * pv1[d];
        }
        k[s][t % DA] = sk; q[s][t % DA] = sq * LOG2E; v[s][t % DA] = sv;
    }
    __syncthreads();

    // ---- stage 6: scores 1 ----
    if (t < TRI) {
        float sum = 0.f;
        #pragma unroll
        for (int a = 0; a < DA; a++) sum += q[tr][a] * k[tc][a];
        att[tr][tc] = ex2(sum);
    }
    __syncthreads();

    // ---- stage 7: AV1 + normalize ----
    if (t < S * DA) {
        int s = t / DA, a = t % DA;
        float sum = 0.f, dot = 0.f;
        for (int c = 0; c <= s; c++) {
            float e = att[s][c];
            sum += e;
            dot += e * v[c][a];
        }
        float iv = rcpa(sum);
        res[s][a] = dot * iv;
        if (a == 0) inv_s[s] = iv;
    }
    __syncthreads();

    // ---- stage 8: proj1 -> h; att rows to output in parallel ----
    if (t < S * D) {
        int s = t / D;
        float r = bf1r;
        #pragma unroll
        for (int a = 0; a < DA; a++) r += res[s][a] * pf1[a];
        h[s][t % D] = r;
    }
    for (int i = t; i < S * S; i += NT) {
        int rr = i / S, cc = i % S;
        out[S * V + i] = (cc <= rr) ? att[rr][cc] * inv_s[rr] : 0.f;
    }
    __syncthreads();

    // ---- stage 9: logits (754 elems, 2 shots) ----
    for (int i = t; i < S * V; i += NT) {
        int s = i / V, vv = i % V;
        float r = bout[vv];
        #pragma unroll
        for (int d = 0; d < D; d++) r += h[s][d] * wout[vv * D + d];
        out[i] = r;
    }
}

extern "C" void kernel_launch(void* const* d_in, const int* in_sizes, int n_in,
                              void* d_out, int out_size)
{
    bes_transformer_kernel<<<1, NT>>>(
        (const int*)  d_in[0],   // x
        (const float*)d_in[1],   // emb_table
        (const float*)d_in[2],   // pos
        (const float*)d_in[3],  (const float*)d_in[4],   // w_k0, b_k0
        (const float*)d_in[5],  (const float*)d_in[6],   // w_q0, b_q0
        (const float*)d_in[7],  (const float*)d_in[8],   // w_v0, b_v0
        (const float*)d_in[9],  (const float*)d_in[10],  // w_f0, b_f0
        (const float*)d_in[11], (const float*)d_in[12],  // w_k1, b_k1
        (const float*)d_in[13], (const float*)d_in[14],  // w_q1, b_q1
        (const float*)d_in[15], (const float*)d_in[16],  // w_v1, b_v1
        (const float*)d_in[17], (const float*)d_in[18],  // w_f1, b_f1
        (const float*)d_in[19], (const float*)d_in[20],  // w_out, b_out
        (float*)d_out);
}